// round 5
// baseline (speedup 1.0000x reference)
#include <cuda_runtime.h>
#include <cstdint>
#include <math.h>

// ---------------- problem constants ----------------
#define BB 32
#define DD 512
#define KK 64
#define TNP 32              // pixels per tile
#define NNPIX 3136
#define NTILES 98           // 3136/32
#define CPB 4               // CTAs per batch
#define THREADS 512

// ---------------- smem layout (floats) ----------------
#define XS_STRIDE 40        // [512][40]  x tile rows (160B, 16B-aligned)
#define WS_STRIDE 520       // [64][520]  w resident (2080B rows, 16B-aligned)
#define AT_STRIDE 72        // [32][72]   logits/alpha [n][k]
#define XS_FLOATS (DD * XS_STRIDE)       // 20480
#define WS_FLOATS (KK * WS_STRIDE)       // 33280
#define AT_FLOATS (TNP * AT_STRIDE)      // 2304
#define ASR_FLOATS (8 * 72)              // 576
#define MB_FLOATS 8                      // two 8B mbarriers + pad
#define SMEM_FLOATS (XS_FLOATS + WS_FLOATS + AT_FLOATS + ASR_FLOATS + MB_FLOATS)
#define SMEM_BYTES (SMEM_FLOATS * 4)     // 226,592 B  (< 232,448 opt-in)

#define XT_BYTES (DD * TNP * 4)          // 65536 per x tile
#define W_BYTES  (KK * DD * 4)           // 131072 (loaded once)

// ---------------- device scratch ----------------
__device__ float g_part[BB * CPB * DD * KK];    // [cta][d][k]
__device__ float g_asum_part[BB * CPB * KK];    // [cta][k]
__device__ float g_y[BB * DD * KK];             // un-normalized vlad [b][d][k]
__device__ float g_red[BB * 16 * KK];           // sumsq slices [b][slice][k]

// m16n8k8 tf32 mma: D = A@B + D. A row-major frag, B col-major frag.
static __device__ __forceinline__ void mma_tf32(float c[4],
        float a0, float a1, float a2, float a3, float b0, float b1) {
    asm volatile(
        "mma.sync.aligned.m16n8k8.row.col.f32.tf32.tf32.f32 "
        "{%0,%1,%2,%3}, {%4,%5,%6,%7}, {%8,%9}, {%0,%1,%2,%3};"
        : "+f"(c[0]), "+f"(c[1]), "+f"(c[2]), "+f"(c[3])
        : "r"(__float_as_uint(a0)), "r"(__float_as_uint(a1)),
          "r"(__float_as_uint(a2)), "r"(__float_as_uint(a3)),
          "r"(__float_as_uint(b0)), "r"(__float_as_uint(b1)));
}

static __device__ __forceinline__ uint32_t smem_u32(const void* p) {
    uint32_t a;
    asm("{ .reg .u64 t; cvta.to.shared.u64 t, %1; cvt.u32.u64 %0, t; }" : "=r"(a) : "l"(p));
    return a;
}
static __device__ __forceinline__ void bulk_cp(uint32_t dst, const void* src,
                                               uint32_t bytes, uint32_t mbar) {
    asm volatile(
        "cp.async.bulk.shared::cluster.global.mbarrier::complete_tx::bytes "
        "[%0], [%1], %2, [%3];"
        :: "r"(dst), "l"(src), "r"(bytes), "r"(mbar) : "memory");
}
#define MBAR_INIT(a, c) asm volatile("mbarrier.init.shared.b64 [%0], %1;" :: "r"(a), "r"(c) : "memory")
#define MBAR_EXPECT(a, tx) asm volatile("mbarrier.arrive.expect_tx.shared.b64 _, [%0], %1;" :: "r"(a), "r"(tx) : "memory")
#define MBAR_WAIT(a, ph) do { \
    uint32_t _m = (a); uint32_t _p = (ph); uint32_t _d; \
    asm volatile("{\n\t.reg .pred p;\n\tmbarrier.try_wait.parity.acquire.cta.shared::cta.b64 p, [%1], %2;\n\tselp.b32 %0,1,0,p;\n\t}" \
        : "=r"(_d) : "r"(_m), "r"(_p) : "memory"); \
    if (!_d) { \
        asm volatile("{\n\t.reg .pred P1;\n\tWL_%=:\n\tmbarrier.try_wait.parity.acquire.cta.shared::cta.b64 P1, [%0], %1, 0x989680;\n\t@P1 bra.uni WD_%=;\n\tbra.uni WL_%=;\n\tWD_%=:\n\t}" \
            :: "r"(_m), "r"(_p) : "memory"); \
    } } while (0)

static __device__ __forceinline__ float trunc_tf32(float v) {
    return __uint_as_float(__float_as_uint(v) & 0xFFFFE000u);
}

// ---------------------------------------------------------------------------
// Fused kernel. grid = 128 (b*4+q), block = 512, 1 CTA/SM.
// w resident in smem; x tiles streamed via cp.async.bulk + mbarrier.
// ---------------------------------------------------------------------------
__global__ void __launch_bounds__(THREADS, 1) fused_kernel(
    const float* __restrict__ x,      // [B, D, N]
    const float* __restrict__ w,      // [K, D]
    const float* __restrict__ bias)   // [K]
{
    extern __shared__ float sm[];
    float* xs    = sm;                       // [512][40]
    float* ws    = xs + XS_FLOATS;           // [64][520]
    float* at    = ws + WS_FLOATS;           // [32][72]
    float* asred = at + AT_FLOATS;           // [8][72]
    float* mbf   = asred + ASR_FLOATS;
    const uint32_t xs_u = smem_u32(xs);
    const uint32_t ws_u = smem_u32(ws);
    const uint32_t xmb  = smem_u32(mbf);
    const uint32_t wmb  = xmb + 8;

    const int tid  = threadIdx.x;
    const int wid  = tid >> 5;               // 0..15
    const int lane = tid & 31;
    const int g    = lane >> 2;              // 0..7
    const int tig  = lane & 3;               // 0..3
    const int b    = blockIdx.x >> 2;
    const int q    = blockIdx.x & 3;

    // GEMM1 warp mapping: 16k x 8n per warp
    const int kb = (wid & 3) * 16;
    const int nb = (wid >> 2) * 8;
    const float bg  = bias[kb + g];
    const float bg8 = bias[kb + g + 8];

    // GEMM2 warp mapping: 32 d (2 m-tiles) x all 64 k per warp
    const int db = wid * 32;

    if (tid == 0) { MBAR_INIT(xmb, 1); MBAR_INIT(wmb, 1); }
    __syncthreads();

    // ---- load w once (64 rows x 2048B bulk copies) --------------------------
    if (tid == 0) MBAR_EXPECT(wmb, W_BYTES);
    __syncthreads();
    if (tid < KK)
        bulk_cp(ws_u + (uint32_t)tid * (WS_STRIDE * 4), w + (size_t)tid * DD,
                DD * 4, wmb);

    // persistent vlad accumulators: [2 m][8 n][4] = 64 regs
    float c2[2][8][4];
#pragma unroll
    for (int mt = 0; mt < 2; ++mt)
#pragma unroll
        for (int nt = 0; nt < 8; ++nt)
#pragma unroll
            for (int r = 0; r < 4; ++r) c2[mt][nt][r] = 0.0f;

    float asum_acc = 0.0f;

    const float* xb = x + (size_t)b * DD * NNPIX;

    int lt = 0;
    for (int t = q; t < NTILES; t += CPB, ++lt) {
        // ---- stream x tile [512][32] via bulk copies (1 row per thread) ----
        if (tid == 0) MBAR_EXPECT(xmb, XT_BYTES);
        __syncthreads();   // prev tile readers of xs/at done + expect visible
        bulk_cp(xs_u + (uint32_t)tid * (XS_STRIDE * 4),
                xb + (size_t)tid * NNPIX + t * TNP, TNP * 4, xmb);

        if (lt == 0) MBAR_WAIT(wmb, 0);
        MBAR_WAIT(xmb, lt & 1);

        // ---- GEMM1: logits[64k][32n] = w @ x --------------------------------
        float c1[4] = {0.0f, 0.0f, 0.0f, 0.0f};
#pragma unroll 8
        for (int ds = 0; ds < 64; ++ds) {
            const int dd = ds * 8;
            float a0 = ws[(kb + g) * WS_STRIDE + dd + tig];
            float a1 = ws[(kb + g + 8) * WS_STRIDE + dd + tig];
            float a2 = ws[(kb + g) * WS_STRIDE + dd + tig + 4];
            float a3 = ws[(kb + g + 8) * WS_STRIDE + dd + tig + 4];
            float b0 = xs[(dd + tig) * XS_STRIDE + nb + g];
            float b1 = xs[(dd + tig + 4) * XS_STRIDE + nb + g];
            mma_tf32(c1, a0, a1, a2, a3, b0, b1);
        }

        // ---- bias + transpose store to at[n][k] ------------------------------
        {
            int n0 = nb + 2 * tig;
            at[n0 * AT_STRIDE + kb + g]           = c1[0] + bg;
            at[(n0 + 1) * AT_STRIDE + kb + g]     = c1[1] + bg;
            at[n0 * AT_STRIDE + kb + g + 8]       = c1[2] + bg8;
            at[(n0 + 1) * AT_STRIDE + kb + g + 8] = c1[3] + bg8;
        }
        __syncthreads();

        // ---- softmax over k per pixel: warp wid -> pixels wid*2, wid*2+1 ----
#pragma unroll
        for (int pp = 0; pp < 2; ++pp) {
            int p = wid * 2 + pp;
            float v0 = at[p * AT_STRIDE + lane];
            float v1 = at[p * AT_STRIDE + lane + 32];
            float m = fmaxf(v0, v1);
#pragma unroll
            for (int off = 16; off > 0; off >>= 1)
                m = fmaxf(m, __shfl_xor_sync(0xFFFFFFFFu, m, off));
            float e0 = __expf(v0 - m);
            float e1 = __expf(v1 - m);
            float s = e0 + e1;
#pragma unroll
            for (int off = 16; off > 0; off >>= 1)
                s += __shfl_xor_sync(0xFFFFFFFFu, s, off);
            float inv = 1.0f / s;
            at[p * AT_STRIDE + lane]      = trunc_tf32(e0 * inv);
            at[p * AT_STRIDE + lane + 32] = trunc_tf32(e1 * inv);
        }
        __syncthreads();

        // ---- asum partial -----------------------------------------------------
        {
            int k = tid & 63;
            int grp = tid >> 6;            // 0..7, 4 pixels each
            float s = 0.0f;
#pragma unroll
            for (int i = 0; i < 4; ++i) s += at[(grp * 4 + i) * AT_STRIDE + k];
            asred[grp * 72 + k] = s;
        }
        __syncthreads();
        if (tid < KK) {
            float s = 0.0f;
#pragma unroll
            for (int i = 0; i < 8; ++i) s += asred[i * 72 + tid];
            asum_acc += s;
        }

        // ---- GEMM2: vlad[d][k] += x[d][n] @ alpha[n][k] -----------------------
#pragma unroll
        for (int ks = 0; ks < 4; ++ks) {
            const int nn = ks * 8;
            float b0[8], b1[8];
#pragma unroll
            for (int nt = 0; nt < 8; ++nt) {
                b0[nt] = at[(nn + tig) * AT_STRIDE + nt * 8 + g];
                b1[nt] = at[(nn + tig + 4) * AT_STRIDE + nt * 8 + g];
            }
#pragma unroll
            for (int mt = 0; mt < 2; ++mt) {
                const int dr = db + mt * 16;
                float a0 = xs[(dr + g) * XS_STRIDE + nn + tig];
                float a1 = xs[(dr + g + 8) * XS_STRIDE + nn + tig];
                float a2 = xs[(dr + g) * XS_STRIDE + nn + tig + 4];
                float a3 = xs[(dr + g + 8) * XS_STRIDE + nn + tig + 4];
#pragma unroll
                for (int nt = 0; nt < 8; ++nt)
                    mma_tf32(c2[mt][nt], a0, a1, a2, a3, b0[nt], b1[nt]);
            }
        }
    }

    if (tid < KK) g_asum_part[blockIdx.x * KK + tid] = asum_acc;

    // ---- epilogue: smem-staged coalesced store of vlad partials --------------
    float* stage = xs;   // reuse: [128][72]
    float* dstb = g_part + (size_t)blockIdx.x * DD * KK;
    for (int chunk = 0; chunk < 4; ++chunk) {
        __syncthreads();
        if ((wid >> 2) == chunk) {
            int lw = wid & 3;
#pragma unroll
            for (int mt = 0; mt < 2; ++mt) {
                int lrow = lw * 32 + mt * 16 + g;
#pragma unroll
                for (int nt = 0; nt < 8; ++nt) {
                    int k0 = nt * 8 + 2 * tig;
                    *(float2*)&stage[lrow * 72 + k0]       = make_float2(c2[mt][nt][0], c2[mt][nt][1]);
                    *(float2*)&stage[(lrow + 8) * 72 + k0] = make_float2(c2[mt][nt][2], c2[mt][nt][3]);
                }
            }
        }
        __syncthreads();
        float* dst = dstb + (size_t)chunk * 128 * KK;
#pragma unroll
        for (int r = 0; r < 4; ++r) {
            int i = tid + r * THREADS;       // 0..2047 float4s
            int dl = i >> 4;
            int k4 = (i & 15) * 4;
            float4 v = *(float4*)&stage[dl * 72 + k4];
            *(float4*)&dst[(size_t)dl * KK + k4] = v;
        }
    }
}

// ---------------------------------------------------------------------------
// Epilogue A: y = sum_q part - centers*asum ; per-slice sumsq partials.
// grid = (16 slices, 32 b), block = 256.
// ---------------------------------------------------------------------------
__global__ void reduce_y_kernel(const float* __restrict__ centers) {
    const int sl = blockIdx.x;
    const int b  = blockIdx.y;
    const int k  = threadIdx.x & 63;
    const int dg = threadIdx.x >> 6;   // 0..3

    float a = g_asum_part[(b * 4 + 0) * KK + k]
            + g_asum_part[(b * 4 + 1) * KK + k]
            + g_asum_part[(b * 4 + 2) * KK + k]
            + g_asum_part[(b * 4 + 3) * KK + k];

    const float* p0 = g_part + (size_t)(b * 4 + 0) * DD * KK;
    const float* p1 = g_part + (size_t)(b * 4 + 1) * DD * KK;
    const float* p2 = g_part + (size_t)(b * 4 + 2) * DD * KK;
    const float* p3 = g_part + (size_t)(b * 4 + 3) * DD * KK;
    float* yb = g_y + (size_t)b * DD * KK;

    float ss = 0.0f;
#pragma unroll
    for (int i = 0; i < 8; ++i) {
        int d = sl * 32 + dg * 8 + i;
        size_t o = (size_t)d * KK + k;
        float y = p0[o] + p1[o] + p2[o] + p3[o] - centers[o] * a;
        yb[o] = y;
        ss += y * y;
    }
    __shared__ float red[4][KK];
    red[dg][k] = ss;
    __syncthreads();
    if (threadIdx.x < KK)
        g_red[(b * 16 + sl) * KK + k] = red[0][k] + red[1][k] + red[2][k] + red[3][k];
}

// ---------------------------------------------------------------------------
// Epilogue B: cnorm + scale. grid = (16, 32), block = 256.
// global L2 norm after intra-normalization == sqrt(K) = 8 (to fp32 eps),
// so fold 1/8 into the per-column scale.
// ---------------------------------------------------------------------------
__global__ void scale_kernel(float* __restrict__ out) {
    const int sl = blockIdx.x;
    const int b  = blockIdx.y;
    __shared__ float cns[KK];
    if (threadIdx.x < KK) {
        float s = 0.0f;
#pragma unroll
        for (int j = 0; j < 16; ++j) s += g_red[(b * 16 + j) * KK + threadIdx.x];
        cns[threadIdx.x] = 0.125f * rsqrtf(s);
    }
    __syncthreads();

    const float* yb = g_y + (size_t)b * DD * KK + (size_t)sl * 32 * KK;
    float* ob = out + (size_t)b * DD * KK + (size_t)sl * 32 * KK;
#pragma unroll
    for (int r = 0; r < 2; ++r) {
        int i = threadIdx.x + r * 256;     // 0..511 float4s
        int k4 = (i & 15) * 4;
        float4 v = *(const float4*)(yb + (size_t)i * 4);
        v.x *= cns[k4];
        v.y *= cns[k4 + 1];
        v.z *= cns[k4 + 2];
        v.w *= cns[k4 + 3];
        *(float4*)(ob + (size_t)i * 4) = v;
    }
}

// ---------------------------------------------------------------------------
extern "C" void kernel_launch(void* const* d_in, const int* in_sizes, int n_in,
                              void* d_out, int out_size) {
    const float* x       = (const float*)d_in[0];
    const float* w       = (const float*)d_in[1];
    const float* bias    = (const float*)d_in[2];
    const float* centers = (const float*)d_in[3];
    float* out = (float*)d_out;

    cudaFuncSetAttribute(fused_kernel,
                         cudaFuncAttributeMaxDynamicSharedMemorySize, SMEM_BYTES);

    fused_kernel<<<BB * CPB, THREADS, SMEM_BYTES>>>(x, w, bias);
    reduce_y_kernel<<<dim3(16, BB), 256>>>(centers);
    scale_kernel<<<dim3(16, BB), 256>>>(out);
}

// round 6
// speedup vs baseline: 1.2624x; 1.2624x over previous
#include <cuda_runtime.h>
#include <cuda_fp16.h>
#include <cstdint>
#include <math.h>

// ---------------- problem constants ----------------
#define BB 32
#define DD 512
#define KK 64
#define TNP 32              // pixels per tile
#define NNPIX 3136
#define NTILES 98           // 3136/32
#define CPB 4               // CTAs per batch
#define THREADS 512

// ---------------- smem byte offsets ----------------
// ws   : fp16 [64][520]   (1040B rows)           66560
// xdn  : fp16 [512][40]   (80B rows, d-major)    40960
// xfull: f32  [512][36]   (144B rows, staging)   73728  (also epilogue stage [128][72] f32)
// at   : f32  [32][72]                            9216
// akp  : fp16 [64][40]    (80B rows, alpha[k][p]) 5120
// asred: f32  [8][72]                             2304
// mbar : 8B
#define WS_OFF    0
#define XDN_OFF   66560
#define XFULL_OFF (XDN_OFF + 40960)        // 107520
#define AT_OFF    (XFULL_OFF + 73728)      // 181248
#define AKP_OFF   (AT_OFF + 9216)          // 190464
#define ASR_OFF   (AKP_OFF + 5120)         // 195584
#define MB_OFF    (ASR_OFF + 2304)         // 197888
#define SMEM_BYTES (MB_OFF + 16)           // 197904

#define XT_BYTES (DD * TNP * 4)            // 65536 per x tile (f32)

// ---------------- device scratch ----------------
__device__ float g_part[BB * CPB * DD * KK];    // [cta][d][k]
__device__ float g_asum_part[BB * CPB * KK];    // [cta][k]
__device__ float g_y[BB * DD * KK];             // [b][d][k]
__device__ float g_red[BB * 16 * KK];           // sumsq slices [b][slice][k]

// m16n8k16 fp16 mma, f32 accum. A row-major frag, B col-major frag.
static __device__ __forceinline__ void mma_f16(float c[4],
        uint32_t a0, uint32_t a1, uint32_t a2, uint32_t a3,
        uint32_t b0, uint32_t b1) {
    asm volatile(
        "mma.sync.aligned.m16n8k16.row.col.f32.f16.f16.f32 "
        "{%0,%1,%2,%3}, {%4,%5,%6,%7}, {%8,%9}, {%0,%1,%2,%3};"
        : "+f"(c[0]), "+f"(c[1]), "+f"(c[2]), "+f"(c[3])
        : "r"(a0), "r"(a1), "r"(a2), "r"(a3), "r"(b0), "r"(b1));
}

static __device__ __forceinline__ uint32_t smem_u32(const void* p) {
    uint32_t a;
    asm("{ .reg .u64 t; cvta.to.shared.u64 t, %1; cvt.u32.u64 %0, t; }" : "=r"(a) : "l"(p));
    return a;
}
static __device__ __forceinline__ void bulk_cp(uint32_t dst, const void* src,
                                               uint32_t bytes, uint32_t mbar) {
    asm volatile(
        "cp.async.bulk.shared::cluster.global.mbarrier::complete_tx::bytes "
        "[%0], [%1], %2, [%3];"
        :: "r"(dst), "l"(src), "r"(bytes), "r"(mbar) : "memory");
}
#define MBAR_INIT(a, c) asm volatile("mbarrier.init.shared.b64 [%0], %1;" :: "r"(a), "r"(c) : "memory")
#define MBAR_EXPECT(a, tx) asm volatile("mbarrier.arrive.expect_tx.shared.b64 _, [%0], %1;" :: "r"(a), "r"(tx) : "memory")
#define MBAR_WAIT(a, ph) do { \
    uint32_t _m = (a); uint32_t _p = (ph); uint32_t _d; \
    asm volatile("{\n\t.reg .pred p;\n\tmbarrier.try_wait.parity.acquire.cta.shared::cta.b64 p, [%1], %2;\n\tselp.b32 %0,1,0,p;\n\t}" \
        : "=r"(_d) : "r"(_m), "r"(_p) : "memory"); \
    if (!_d) { \
        asm volatile("{\n\t.reg .pred P1;\n\tWL_%=:\n\tmbarrier.try_wait.parity.acquire.cta.shared::cta.b64 P1, [%0], %1, 0x989680;\n\t@P1 bra.uni WD_%=;\n\tbra.uni WL_%=;\n\tWD_%=:\n\t}" \
            :: "r"(_m), "r"(_p) : "memory"); \
    } } while (0)

// ---------------------------------------------------------------------------
// Fused kernel. grid = 128 (b*4+q), block = 512, 1 CTA/SM.
// ---------------------------------------------------------------------------
__global__ void __launch_bounds__(THREADS, 1) fused_kernel(
    const float* __restrict__ x,      // [B, D, N]
    const float* __restrict__ w,      // [K, D]
    const float* __restrict__ bias)   // [K]
{
    extern __shared__ char sm[];
    __half* ws    = (__half*)(sm + WS_OFF);     // [64][520]
    __half* xdn   = (__half*)(sm + XDN_OFF);    // [512][40]
    float*  xfull = (float*)(sm + XFULL_OFF);   // [512][36]
    float*  at    = (float*)(sm + AT_OFF);      // [32][72]
    __half* akp   = (__half*)(sm + AKP_OFF);    // [64][40]
    float*  asred = (float*)(sm + ASR_OFF);     // [8][72]
    const uint32_t xdn_u   = smem_u32(xdn);
    const uint32_t xfull_u = smem_u32(xfull);
    const uint32_t xmb     = smem_u32(sm + MB_OFF);

    const int tid  = threadIdx.x;
    const int wid  = tid >> 5;               // 0..15
    const int lane = tid & 31;
    const int g    = lane >> 2;               // 0..7
    const int tg   = lane & 3;                // 0..3
    const int b    = blockIdx.x >> 2;
    const int q    = blockIdx.x & 3;

    // GEMM1 (logits^T[pixel][kc]): m-tile = pixel half, n-tile = kc octet
    const int p0 = (wid & 1) * 16;
    const int n0 = (wid >> 1) * 8;
    const float bias0 = bias[n0 + 2 * tg];
    const float bias1 = bias[n0 + 2 * tg + 1];
    // ldmatrix.x4.trans per-lane base address into xdn (16x16 d x pixel tile)
    const uint32_t lm_base = xdn_u
        + (uint32_t)(((lane >> 4) * 8 + (lane & 7)) * 80
                     + (p0 + ((lane >> 3) & 1) * 8) * 2);

    // GEMM2 (vlad^T[kc][d]): m-tile = kc (wid&3), d span = (wid>>2)*128
    const int kb2   = (wid & 3) * 16;
    const int dbase = (wid >> 2) * 128;

    if (tid == 0) MBAR_INIT(xmb, 1);

    // ---- convert w -> fp16 ws[64][520] once ---------------------------------
#pragma unroll
    for (int r = 0; r < 16; ++r) {
        int idx = tid + r * THREADS;           // 8192 float4s (64 x 128)
        int k = idx >> 7;
        int j = idx & 127;
        float4 v = *(const float4*)(w + (size_t)k * DD + j * 4);
        __half2 h0 = __floats2half2_rn(v.x, v.y);
        __half2 h1 = __floats2half2_rn(v.z, v.w);
        char* dst = (char*)ws + k * 1040 + j * 8;
        *(__half2*)dst = h0;
        *(__half2*)(dst + 4) = h1;
    }
    __syncthreads();                           // ws + mbar init visible

    // ---- prefetch first x tile ----------------------------------------------
    const float* xg = x + (size_t)b * DD * NNPIX;
    if (tid == 0) MBAR_EXPECT(xmb, XT_BYTES);
    __syncthreads();
    bulk_cp(xfull_u + (uint32_t)tid * 144, xg + (size_t)tid * NNPIX + q * TNP,
            TNP * 4, xmb);

    // persistent vlad^T accumulators: [16 d-tiles][4] = 64 regs
    float c2[16][4];
#pragma unroll
    for (int j = 0; j < 16; ++j)
#pragma unroll
        for (int r = 0; r < 4; ++r) c2[j][r] = 0.0f;

    float asum_acc = 0.0f;
    int lt = 0;
    for (int t = q; t < NTILES; t += CPB, ++lt) {
        __syncthreads();                       // (A) prev-tile consumers done

        if (lt > 0 && tid < KK) {              // reduce prev tile's asred
            float s = 0.0f;
#pragma unroll
            for (int i = 0; i < 8; ++i) s += asred[i * 72 + tid];
            asum_acc += s;
        }

        MBAR_WAIT(xmb, lt & 1);                // x tile (f32) ready in xfull
        const bool has_next = (t + CPB < NTILES);
        if (has_next && tid == 0) MBAR_EXPECT(xmb, XT_BYTES);

        // ---- convert xfull f32 -> xdn fp16 (thread = d row) -----------------
        {
            const float4* src = (const float4*)(xfull + tid * 36);
            uint4 o[4];
#pragma unroll
            for (int jj = 0; jj < 4; ++jj) {
                float4 v0 = src[2 * jj];
                float4 v1 = src[2 * jj + 1];
                __half2 h0 = __floats2half2_rn(v0.x, v0.y);
                __half2 h1 = __floats2half2_rn(v0.z, v0.w);
                __half2 h2 = __floats2half2_rn(v1.x, v1.y);
                __half2 h3 = __floats2half2_rn(v1.z, v1.w);
                o[jj].x = *(uint32_t*)&h0; o[jj].y = *(uint32_t*)&h1;
                o[jj].z = *(uint32_t*)&h2; o[jj].w = *(uint32_t*)&h3;
            }
            uint4* dst = (uint4*)((char*)xdn + tid * 80);
#pragma unroll
            for (int jj = 0; jj < 4; ++jj) dst[jj] = o[jj];
        }
        __syncthreads();                       // (B) xdn ready, xfull free

        if (has_next)
            bulk_cp(xfull_u + (uint32_t)tid * 144,
                    xg + (size_t)tid * NNPIX + (t + CPB) * TNP, TNP * 4, xmb);

        // ---- GEMM1: logits^T[32p][64k] = x^T @ w^T ---------------------------
        {
            float c1[4] = {0.0f, 0.0f, 0.0f, 0.0f};
            const char* wsrow = (const char*)ws + (n0 + g) * 1040 + tg * 4;
#pragma unroll
            for (int ks = 0; ks < 32; ++ks) {
                uint32_t a0, a1, a2, a3;
                asm volatile(
                    "ldmatrix.sync.aligned.m8n8.x4.trans.shared.b16 "
                    "{%0,%1,%2,%3}, [%4];"
                    : "=r"(a0), "=r"(a1), "=r"(a2), "=r"(a3)
                    : "r"(lm_base + (uint32_t)ks * 1280));
                uint32_t b0 = *(const uint32_t*)(wsrow + ks * 32);
                uint32_t b1 = *(const uint32_t*)(wsrow + ks * 32 + 16);
                mma_f16(c1, a0, a1, a2, a3, b0, b1);
            }
            float* atp = at + (p0 + g) * 72 + n0 + 2 * tg;
            atp[0] = c1[0] + bias0;
            atp[1] = c1[1] + bias1;
            atp[8 * 72] = c1[2] + bias0;
            atp[8 * 72 + 1] = c1[3] + bias1;
        }
        __syncthreads();                       // (C) logits staged

        // ---- softmax over k per pixel: warp wid -> pixels 2wid, 2wid+1 ------
#pragma unroll
        for (int pp = 0; pp < 2; ++pp) {
            int p = wid * 2 + pp;
            float v0 = at[p * 72 + lane];
            float v1 = at[p * 72 + lane + 32];
            float m = fmaxf(v0, v1);
#pragma unroll
            for (int off = 16; off > 0; off >>= 1)
                m = fmaxf(m, __shfl_xor_sync(0xFFFFFFFFu, m, off));
            float e0 = __expf(v0 - m);
            float e1 = __expf(v1 - m);
            float s = e0 + e1;
#pragma unroll
            for (int off = 16; off > 0; off >>= 1)
                s += __shfl_xor_sync(0xFFFFFFFFu, s, off);
            float inv = 1.0f / s;
            akp[lane * 40 + p]        = __float2half_rn(e0 * inv);
            akp[(lane + 32) * 40 + p] = __float2half_rn(e1 * inv);
        }
        __syncthreads();                       // (D) alpha ready

        // ---- asum partials (from the fp16 alpha GEMM2 consumes) -------------
        {
            int k = tid & 63;
            int grp = tid >> 6;                // 4 pixels each
            const __half2* ph = (const __half2*)((const char*)akp + k * 80 + grp * 8);
            float2 f0 = __half22float2(ph[0]);
            float2 f1 = __half22float2(ph[1]);
            asred[grp * 72 + k] = (f0.x + f0.y) + (f1.x + f1.y);
        }

        // ---- GEMM2: vlad^T[64k][512d] += alpha[64k x 32p] @ x^T[32p x 512d] --
        {
            const char* akpb = (const char*)akp + (kb2 + g) * 80 + tg * 4;
            const char* xb2  = (const char*)xdn + (dbase + g) * 80 + tg * 4;
#pragma unroll
            for (int s = 0; s < 2; ++s) {
                const int so = s * 32;         // 16 pixels * 2B
                uint32_t a0 = *(const uint32_t*)(akpb + so);
                uint32_t a1 = *(const uint32_t*)(akpb + 640 + so);
                uint32_t a2 = *(const uint32_t*)(akpb + so + 16);
                uint32_t a3 = *(const uint32_t*)(akpb + 640 + so + 16);
#pragma unroll
                for (int j = 0; j < 16; ++j) {
                    uint32_t b0 = *(const uint32_t*)(xb2 + j * 640 + so);
                    uint32_t b1 = *(const uint32_t*)(xb2 + j * 640 + so + 16);
                    mma_f16(c2[j], a0, a1, a2, a3, b0, b1);
                }
            }
        }
    }

    __syncthreads();
    if (tid < KK) {                            // last tile's asred
        float s = 0.0f;
#pragma unroll
        for (int i = 0; i < 8; ++i) s += asred[i * 72 + tid];
        g_asum_part[blockIdx.x * KK + tid] = asum_acc + s;
    }

    // ---- epilogue: transpose-stage vlad^T -> g_part[cta][d][k] --------------
    float* stage = xfull;                      // [128][72] f32
    float* dstb = g_part + (size_t)blockIdx.x * DD * KK;
    for (int chunk = 0; chunk < 4; ++chunk) {
        __syncthreads();
        if ((wid >> 2) == chunk) {
#pragma unroll
            for (int j = 0; j < 16; ++j) {
                int dl = 8 * j + 2 * tg;
                stage[dl * 72 + kb2 + g]           = c2[j][0];
                stage[(dl + 1) * 72 + kb2 + g]     = c2[j][1];
                stage[dl * 72 + kb2 + g + 8]       = c2[j][2];
                stage[(dl + 1) * 72 + kb2 + g + 8] = c2[j][3];
            }
        }
        __syncthreads();
        float* dst = dstb + (size_t)chunk * 128 * KK;
#pragma unroll
        for (int r = 0; r < 4; ++r) {
            int i = tid + r * THREADS;         // 2048 float4s
            int dl = i >> 4;
            int k4 = (i & 15) * 4;
            float4 v = *(float4*)&stage[dl * 72 + k4];
            *(float4*)&dst[(size_t)dl * KK + k4] = v;
        }
    }
}

// ---------------------------------------------------------------------------
// Epilogue A: y = sum_q part - centers*asum ; per-slice sumsq partials.
// grid = (16, 32), block = 256.
// ---------------------------------------------------------------------------
__global__ void reduce_y_kernel(const float* __restrict__ centers) {
    const int sl = blockIdx.x;
    const int b  = blockIdx.y;
    const int k  = threadIdx.x & 63;
    const int dg = threadIdx.x >> 6;

    float a = g_asum_part[(b * 4 + 0) * KK + k]
            + g_asum_part[(b * 4 + 1) * KK + k]
            + g_asum_part[(b * 4 + 2) * KK + k]
            + g_asum_part[(b * 4 + 3) * KK + k];

    const float* p0 = g_part + (size_t)(b * 4 + 0) * DD * KK;
    const float* p1 = g_part + (size_t)(b * 4 + 1) * DD * KK;
    const float* p2 = g_part + (size_t)(b * 4 + 2) * DD * KK;
    const float* p3 = g_part + (size_t)(b * 4 + 3) * DD * KK;
    float* yb = g_y + (size_t)b * DD * KK;

    float ss = 0.0f;
#pragma unroll
    for (int i = 0; i < 8; ++i) {
        int d = sl * 32 + dg * 8 + i;
        size_t o = (size_t)d * KK + k;
        float y = p0[o] + p1[o] + p2[o] + p3[o] - centers[o] * a;
        yb[o] = y;
        ss += y * y;
    }
    __shared__ float red[4][KK];
    red[dg][k] = ss;
    __syncthreads();
    if (threadIdx.x < KK)
        g_red[(b * 16 + sl) * KK + k] = red[0][k] + red[1][k] + red[2][k] + red[3][k];
}

// ---------------------------------------------------------------------------
// Epilogue B: cnorm + scale. grid = (16, 32), block = 256.
// Global L2 norm after intra-normalization == sqrt(K)=8 (to fp32 eps),
// so fold 1/8 into the per-column scale.
// ---------------------------------------------------------------------------
__global__ void scale_kernel(float* __restrict__ out) {
    const int sl = blockIdx.x;
    const int b  = blockIdx.y;
    __shared__ float cns[KK];
    if (threadIdx.x < KK) {
        float s = 0.0f;
#pragma unroll
        for (int j = 0; j < 16; ++j) s += g_red[(b * 16 + j) * KK + threadIdx.x];
        cns[threadIdx.x] = 0.125f * rsqrtf(s);
    }
    __syncthreads();

    const float* yb = g_y + (size_t)b * DD * KK + (size_t)sl * 32 * KK;
    float* ob = out + (size_t)b * DD * KK + (size_t)sl * 32 * KK;
#pragma unroll
    for (int r = 0; r < 2; ++r) {
        int i = threadIdx.x + r * 256;
        int k4 = (i & 15) * 4;
        float4 v = *(const float4*)(yb + (size_t)i * 4);
        v.x *= cns[k4];
        v.y *= cns[k4 + 1];
        v.z *= cns[k4 + 2];
        v.w *= cns[k4 + 3];
        *(float4*)(ob + (size_t)i * 4) = v;
    }
}

// ---------------------------------------------------------------------------
extern "C" void kernel_launch(void* const* d_in, const int* in_sizes, int n_in,
                              void* d_out, int out_size) {
    const float* x       = (const float*)d_in[0];
    const float* w       = (const float*)d_in[1];
    const float* bias    = (const float*)d_in[2];
    const float* centers = (const float*)d_in[3];
    float* out = (float*)d_out;

    cudaFuncSetAttribute(fused_kernel,
                         cudaFuncAttributeMaxDynamicSharedMemorySize, SMEM_BYTES);

    fused_kernel<<<BB * CPB, THREADS, SMEM_BYTES>>>(x, w, bias);
    reduce_y_kernel<<<dim3(16, BB), 256>>>(centers);
    scale_kernel<<<dim3(16, BB), 256>>>(out);
}

// round 7
// speedup vs baseline: 2.1581x; 1.7096x over previous
#include <cuda_runtime.h>
#include <cuda_fp16.h>
#include <cstdint>
#include <math.h>

// ---------------- problem constants ----------------
#define BB 32
#define DD 512
#define KK 64
#define TNP 64              // pixels per tile
#define NNPIX 3136
#define NTILES 49           // 3136/64
#define CPB 4               // CTAs per batch
#define THREADS 512

// ---------------- smem byte offsets ----------------
// ws  : fp16 [64][520]  (1040B rows)                    66560
// xdn : fp16 [512][72]  (144B rows, d-major)            73728  (epilogue: f32 stage [128][72])
// at  : f32  [64][68]   (272B rows, logits [px][k])     17408
// akp : fp16 [64][72]   (144B rows, alpha [k][px])       9216
// asred: f32 [8][72]                                     2304
#define WS_OFF    0
#define XDN_OFF   66560
#define AT_OFF    (XDN_OFF + 73728)        // 140288
#define AKP_OFF   (AT_OFF + 17408)         // 157696
#define ASR_OFF   (AKP_OFF + 9216)         // 166912
#define SMEM_BYTES (ASR_OFF + 2304 + 16)   // 169232

// ---------------- device scratch ----------------
__device__ float g_part[BB * CPB * DD * KK];    // [cta][d][k]
__device__ float g_asum_part[BB * CPB * KK];    // [cta][k]
__device__ float g_y[BB * DD * KK];             // [b][d][k]
__device__ float g_red[BB * 16 * KK];           // sumsq slices [b][slice][k]

// m16n8k16 fp16 mma, f32 accum.
static __device__ __forceinline__ void mma_f16(float c[4],
        uint32_t a0, uint32_t a1, uint32_t a2, uint32_t a3,
        uint32_t b0, uint32_t b1) {
    asm volatile(
        "mma.sync.aligned.m16n8k16.row.col.f32.f16.f16.f32 "
        "{%0,%1,%2,%3}, {%4,%5,%6,%7}, {%8,%9}, {%0,%1,%2,%3};"
        : "+f"(c[0]), "+f"(c[1]), "+f"(c[2]), "+f"(c[3])
        : "r"(a0), "r"(a1), "r"(a2), "r"(a3), "r"(b0), "r"(b1));
}

static __device__ __forceinline__ uint32_t smem_u32(const void* p) {
    uint32_t a;
    asm("{ .reg .u64 t; cvta.to.shared.u64 t, %1; cvt.u32.u64 %0, t; }" : "=r"(a) : "l"(p));
    return a;
}

// ---------------------------------------------------------------------------
// Fused kernel. grid = 128 (b*4+q), block = 512, 1 CTA/SM.
// ---------------------------------------------------------------------------
__global__ void __launch_bounds__(THREADS, 1) fused_kernel(
    const float* __restrict__ x,      // [B, D, N]
    const float* __restrict__ w,      // [K, D]
    const float* __restrict__ bias)   // [K]
{
    extern __shared__ char sm[];
    __half* ws    = (__half*)(sm + WS_OFF);     // [64][520]
    char*   xdn   = sm + XDN_OFF;               // fp16 [512] rows of 144B
    float*  at    = (float*)(sm + AT_OFF);      // [64][68]
    char*   akp   = sm + AKP_OFF;               // fp16 [64] rows of 144B
    float*  asred = (float*)(sm + ASR_OFF);     // [8][72]
    const uint32_t xdn_u = smem_u32(xdn);

    const int tid  = threadIdx.x;
    const int wid  = tid >> 5;               // 0..15
    const int lane = tid & 31;
    const int g    = lane >> 2;               // 0..7
    const int tg   = lane & 3;                // 0..3
    const int b    = blockIdx.x >> 2;
    const int q    = blockIdx.x & 3;

    // GEMM1 (logits^T[px][k]): m-tile = 16 px (wid&3), n-tiles n0, n0+8
    const int p0 = (wid & 3) * 16;
    const int n0 = (wid >> 2) * 16;
    const float bias_a0 = bias[n0 + 2 * tg];
    const float bias_a1 = bias[n0 + 2 * tg + 1];
    const float bias_b0 = bias[n0 + 8 + 2 * tg];
    const float bias_b1 = bias[n0 + 8 + 2 * tg + 1];
    // ldmatrix.x4.trans per-lane address (16d x 16px tile at d=0)
    const uint32_t lm_base = xdn_u
        + (uint32_t)(((lane >> 4) * 8 + (lane & 7)) * 144
                     + (p0 + ((lane >> 3) & 1) * 8) * 2);

    // GEMM2 (vlad^T[k][d]): m-tile = 16 k (wid&3), d span = (wid>>2)*128
    const int kb2   = (wid & 3) * 16;
    const int dbase = (wid >> 2) * 128;

    // ---- convert w -> fp16 ws[64][520] once ---------------------------------
#pragma unroll
    for (int r = 0; r < 16; ++r) {
        int idx = tid + r * THREADS;           // 8192 float4s (64 x 128)
        int k = idx >> 7;
        int j = idx & 127;
        float4 v = *(const float4*)(w + (size_t)k * DD + j * 4);
        __half2 h0 = __floats2half2_rn(v.x, v.y);
        __half2 h1 = __floats2half2_rn(v.z, v.w);
        char* dst = (char*)ws + k * 1040 + j * 8;
        *(__half2*)dst = h0;
        *(__half2*)(dst + 4) = h1;
    }

    // persistent vlad^T accumulators: [16 d-subtiles][4] = 64 regs
    float c2[16][4];
#pragma unroll
    for (int j = 0; j < 16; ++j)
#pragma unroll
        for (int r = 0; r < 4; ++r) c2[j][r] = 0.0f;

    float asum_acc = 0.0f;
    const float* xg = x + (size_t)b * DD * NNPIX;
    const int jj = tid & 15;                   // 16B chunk within row
    const int r0 = tid >> 4;                   // row base (32 rows per pass)

    int lt = 0;
    for (int t = q; t < NTILES; t += CPB, ++lt) {
        __syncthreads();                       // (A) prev consumers of xdn/akp done

        if (lt > 0 && tid < KK) {              // reduce prev tile's asred
            float s = 0.0f;
#pragma unroll
            for (int i = 0; i < 8; ++i) s += asred[i * 72 + tid];
            asum_acc += s;
        }

        // ---- load + convert x tile [512 d][64 px] f32 -> fp16 ---------------
        // half-warp per row: coalesced 256B/row LDG; STS.64 per thread.
#pragma unroll
        for (int pass = 0; pass < 16; ++pass) {
            int r = pass * 32 + r0;
            float4 v = *(const float4*)(xg + (size_t)r * NNPIX + t * TNP + jj * 4);
            __half2 h0 = __floats2half2_rn(v.x, v.y);
            __half2 h1 = __floats2half2_rn(v.z, v.w);
            uint2 u = { *(uint32_t*)&h0, *(uint32_t*)&h1 };
            *(uint2*)(xdn + r * 144 + jj * 8) = u;
        }
        __syncthreads();                       // (B) xdn ready (iter0: ws also)

        // ---- GEMM1: logits^T[64px][64k] = x^T @ w^T --------------------------
        {
            float c1a[4] = {0.f, 0.f, 0.f, 0.f};
            float c1b[4] = {0.f, 0.f, 0.f, 0.f};
            const char* w0 = (const char*)ws + (n0 + g) * 1040 + tg * 4;
            const char* w1 = (const char*)ws + (n0 + 8 + g) * 1040 + tg * 4;
#pragma unroll
            for (int ks = 0; ks < 32; ++ks) {
                uint32_t a0, a1, a2, a3;
                asm volatile(
                    "ldmatrix.sync.aligned.m8n8.x4.trans.shared.b16 "
                    "{%0,%1,%2,%3}, [%4];"
                    : "=r"(a0), "=r"(a1), "=r"(a2), "=r"(a3)
                    : "r"(lm_base + (uint32_t)ks * 2304));
                uint32_t b0 = *(const uint32_t*)(w0 + ks * 32);
                uint32_t b1 = *(const uint32_t*)(w0 + ks * 32 + 16);
                mma_f16(c1a, a0, a1, a2, a3, b0, b1);
                uint32_t b2 = *(const uint32_t*)(w1 + ks * 32);
                uint32_t b3 = *(const uint32_t*)(w1 + ks * 32 + 16);
                mma_f16(c1b, a0, a1, a2, a3, b2, b3);
            }
            float* atp = at + (p0 + g) * 68;
            atp[n0 + 2 * tg]              = c1a[0] + bias_a0;
            atp[n0 + 2 * tg + 1]          = c1a[1] + bias_a1;
            atp[8 * 68 + n0 + 2 * tg]     = c1a[2] + bias_a0;
            atp[8 * 68 + n0 + 2 * tg + 1] = c1a[3] + bias_a1;
            atp[n0 + 8 + 2 * tg]              = c1b[0] + bias_b0;
            atp[n0 + 8 + 2 * tg + 1]          = c1b[1] + bias_b1;
            atp[8 * 68 + n0 + 8 + 2 * tg]     = c1b[2] + bias_b0;
            atp[8 * 68 + n0 + 8 + 2 * tg + 1] = c1b[3] + bias_b1;
        }
        __syncthreads();                       // (C) logits staged

        // ---- softmax over k per pixel: warp wid -> pixels 4wid..4wid+3 ------
#pragma unroll
        for (int pp = 0; pp < 4; ++pp) {
            int p = wid * 4 + pp;
            float v0 = at[p * 68 + lane];
            float v1 = at[p * 68 + lane + 32];
            float m = fmaxf(v0, v1);
#pragma unroll
            for (int off = 16; off > 0; off >>= 1)
                m = fmaxf(m, __shfl_xor_sync(0xFFFFFFFFu, m, off));
            float e0 = __expf(v0 - m);
            float e1 = __expf(v1 - m);
            float s = e0 + e1;
#pragma unroll
            for (int off = 16; off > 0; off >>= 1)
                s += __shfl_xor_sync(0xFFFFFFFFu, s, off);
            float inv = 1.0f / s;
            *(__half*)(akp + lane * 144 + p * 2)        = __float2half_rn(e0 * inv);
            *(__half*)(akp + (lane + 32) * 144 + p * 2) = __float2half_rn(e1 * inv);
        }
        __syncthreads();                       // (D) alpha ready

        // ---- asum partials (fp16 alpha, 8 px per thread) ---------------------
        {
            int k = tid & 63;
            int grp = tid >> 6;                // 0..7
            uint4 u = *(const uint4*)(akp + k * 144 + grp * 16);
            float2 f0 = __half22float2(*(__half2*)&u.x);
            float2 f1 = __half22float2(*(__half2*)&u.y);
            float2 f2 = __half22float2(*(__half2*)&u.z);
            float2 f3 = __half22float2(*(__half2*)&u.w);
            asred[grp * 72 + k] = (f0.x + f0.y) + (f1.x + f1.y)
                                + (f2.x + f2.y) + (f3.x + f3.y);
        }

        // ---- GEMM2: vlad^T[64k][512d] += alpha[64k x 64p] @ x^T[64p x 512d] --
        {
            const char* akpb = akp + (kb2 + g) * 144 + tg * 4;
            const char* xb2  = xdn + (dbase + g) * 144 + tg * 4;
#pragma unroll
            for (int s = 0; s < 4; ++s) {
                const int so = s * 32;         // 16 pixels * 2B
                uint32_t a0 = *(const uint32_t*)(akpb + so);
                uint32_t a1 = *(const uint32_t*)(akpb + 1152 + so);
                uint32_t a2 = *(const uint32_t*)(akpb + so + 16);
                uint32_t a3 = *(const uint32_t*)(akpb + 1152 + so + 16);
#pragma unroll
                for (int j = 0; j < 16; ++j) {
                    uint32_t b0 = *(const uint32_t*)(xb2 + j * 1152 + so);
                    uint32_t b1 = *(const uint32_t*)(xb2 + j * 1152 + so + 16);
                    mma_f16(c2[j], a0, a1, a2, a3, b0, b1);
                }
            }
        }
    }

    __syncthreads();
    if (tid < KK) {                            // last tile's asred
        float s = 0.0f;
#pragma unroll
        for (int i = 0; i < 8; ++i) s += asred[i * 72 + tid];
        g_asum_part[blockIdx.x * KK + tid] = asum_acc + s;
    }

    // ---- epilogue: transpose-stage vlad^T -> g_part[cta][d][k] --------------
    float* stage = (float*)xdn;                // [128][72] f32
    float* dstb = g_part + (size_t)blockIdx.x * DD * KK;
    for (int chunk = 0; chunk < 4; ++chunk) {
        __syncthreads();
        if ((wid >> 2) == chunk) {
#pragma unroll
            for (int j = 0; j < 16; ++j) {
                int dl = 8 * j + 2 * tg;
                stage[dl * 72 + kb2 + g]           = c2[j][0];
                stage[(dl + 1) * 72 + kb2 + g]     = c2[j][1];
                stage[dl * 72 + kb2 + g + 8]       = c2[j][2];
                stage[(dl + 1) * 72 + kb2 + g + 8] = c2[j][3];
            }
        }
        __syncthreads();
        float* dst = dstb + (size_t)chunk * 128 * KK;
#pragma unroll
        for (int r = 0; r < 4; ++r) {
            int i = tid + r * THREADS;         // 2048 float4s
            int dl = i >> 4;
            int k4 = (i & 15) * 4;
            float4 v = *(float4*)&stage[dl * 72 + k4];
            *(float4*)&dst[(size_t)dl * KK + k4] = v;
        }
    }
}

// ---------------------------------------------------------------------------
// Epilogue A: y = sum_q part - centers*asum ; per-slice sumsq partials.
// grid = (16, 32), block = 256.
// ---------------------------------------------------------------------------
__global__ void reduce_y_kernel(const float* __restrict__ centers) {
    const int sl = blockIdx.x;
    const int b  = blockIdx.y;
    const int k  = threadIdx.x & 63;
    const int dg = threadIdx.x >> 6;

    float a = g_asum_part[(b * 4 + 0) * KK + k]
            + g_asum_part[(b * 4 + 1) * KK + k]
            + g_asum_part[(b * 4 + 2) * KK + k]
            + g_asum_part[(b * 4 + 3) * KK + k];

    const float* p0 = g_part + (size_t)(b * 4 + 0) * DD * KK;
    const float* p1 = g_part + (size_t)(b * 4 + 1) * DD * KK;
    const float* p2 = g_part + (size_t)(b * 4 + 2) * DD * KK;
    const float* p3 = g_part + (size_t)(b * 4 + 3) * DD * KK;
    float* yb = g_y + (size_t)b * DD * KK;

    float ss = 0.0f;
#pragma unroll
    for (int i = 0; i < 8; ++i) {
        int d = sl * 32 + dg * 8 + i;
        size_t o = (size_t)d * KK + k;
        float y = p0[o] + p1[o] + p2[o] + p3[o] - centers[o] * a;
        yb[o] = y;
        ss += y * y;
    }
    __shared__ float red[4][KK];
    red[dg][k] = ss;
    __syncthreads();
    if (threadIdx.x < KK)
        g_red[(b * 16 + sl) * KK + k] = red[0][k] + red[1][k] + red[2][k] + red[3][k];
}

// ---------------------------------------------------------------------------
// Epilogue B: cnorm + scale. grid = (16, 32), block = 256.
// Global L2 norm after intra-normalization == sqrt(K)=8 (to fp32 eps),
// so fold 1/8 into the per-column scale.
// ---------------------------------------------------------------------------
__global__ void scale_kernel(float* __restrict__ out) {
    const int sl = blockIdx.x;
    const int b  = blockIdx.y;
    __shared__ float cns[KK];
    if (threadIdx.x < KK) {
        float s = 0.0f;
#pragma unroll
        for (int j = 0; j < 16; ++j) s += g_red[(b * 16 + j) * KK + threadIdx.x];
        cns[threadIdx.x] = 0.125f * rsqrtf(s);
    }
    __syncthreads();

    const float* yb = g_y + (size_t)b * DD * KK + (size_t)sl * 32 * KK;
    float* ob = out + (size_t)b * DD * KK + (size_t)sl * 32 * KK;
#pragma unroll
    for (int r = 0; r < 2; ++r) {
        int i = threadIdx.x + r * 256;
        int k4 = (i & 15) * 4;
        float4 v = *(const float4*)(yb + (size_t)i * 4);
        v.x *= cns[k4];
        v.y *= cns[k4 + 1];
        v.z *= cns[k4 + 2];
        v.w *= cns[k4 + 3];
        *(float4*)(ob + (size_t)i * 4) = v;
    }
}

// ---------------------------------------------------------------------------
extern "C" void kernel_launch(void* const* d_in, const int* in_sizes, int n_in,
                              void* d_out, int out_size) {
    const float* x       = (const float*)d_in[0];
    const float* w       = (const float*)d_in[1];
    const float* bias    = (const float*)d_in[2];
    const float* centers = (const float*)d_in[3];
    float* out = (float*)d_out;

    cudaFuncSetAttribute(fused_kernel,
                         cudaFuncAttributeMaxDynamicSharedMemorySize, SMEM_BYTES);

    fused_kernel<<<BB * CPB, THREADS, SMEM_BYTES>>>(x, w, bias);
    reduce_y_kernel<<<dim3(16, BB), 256>>>(centers);
    scale_kernel<<<dim3(16, BB), 256>>>(out);
}

// round 8
// speedup vs baseline: 2.3218x; 1.0758x over previous
#include <cuda_runtime.h>
#include <cuda_fp16.h>
#include <cstdint>
#include <math.h>

// ---------------- problem constants ----------------
#define BB 32
#define DD 512
#define KK 64
#define TNP 64              // pixels per tile
#define NNPIX 3136
#define NTILES 49           // 3136/64
#define CPB 4               // CTAs per batch
#define THREADS 512

// ---------------- smem byte offsets ----------------
#define WS_OFF    0                        // fp16 [64][520]  (1040B rows)
#define XDN_OFF   66560                    // fp16 [512] rows of 144B
#define AT_OFF    (XDN_OFF + 73728)        // f32  [64][68]
#define AKP_OFF   (AT_OFF + 17408)         // fp16 [64] rows of 144B
#define ASR_OFF   (AKP_OFF + 9216)         // f32  [8][72]
#define SMEM_BYTES (ASR_OFF + 2304 + 16)   // 169232

// ---------------- device scratch ----------------
__device__ float g_part[BB * CPB * DD * KK];    // [cta][d][k]
__device__ float g_asum_part[BB * CPB * KK];    // [cta][k]
__device__ float g_y[BB * DD * KK];             // [b][d][k]
__device__ float g_red[BB * 16 * KK];           // sumsq slices [b][slice][k]

// m16n8k16 fp16 mma, f32 accum.
static __device__ __forceinline__ void mma_f16(float c[4],
        uint32_t a0, uint32_t a1, uint32_t a2, uint32_t a3,
        uint32_t b0, uint32_t b1) {
    asm volatile(
        "mma.sync.aligned.m16n8k16.row.col.f32.f16.f16.f32 "
        "{%0,%1,%2,%3}, {%4,%5,%6,%7}, {%8,%9}, {%0,%1,%2,%3};"
        : "+f"(c[0]), "+f"(c[1]), "+f"(c[2]), "+f"(c[3])
        : "r"(a0), "r"(a1), "r"(a2), "r"(a3), "r"(b0), "r"(b1));
}
#define LDSM4(r0, r1, r2, r3, addr) \
    asm volatile("ldmatrix.sync.aligned.m8n8.x4.shared.b16 {%0,%1,%2,%3}, [%4];" \
        : "=r"(r0), "=r"(r1), "=r"(r2), "=r"(r3) : "r"(addr))
#define LDSM4T(r0, r1, r2, r3, addr) \
    asm volatile("ldmatrix.sync.aligned.m8n8.x4.trans.shared.b16 {%0,%1,%2,%3}, [%4];" \
        : "=r"(r0), "=r"(r1), "=r"(r2), "=r"(r3) : "r"(addr))

static __device__ __forceinline__ uint32_t smem_u32(const void* p) {
    uint32_t a;
    asm("{ .reg .u64 t; cvta.to.shared.u64 t, %1; cvt.u32.u64 %0, t; }" : "=r"(a) : "l"(p));
    return a;
}
static __device__ __forceinline__ uint2 cvt_f4h(float4 v) {
    __half2 h0 = __floats2half2_rn(v.x, v.y);
    __half2 h1 = __floats2half2_rn(v.z, v.w);
    uint2 u;
    u.x = *(uint32_t*)&h0;
    u.y = *(uint32_t*)&h1;
    return u;
}

// ---------------------------------------------------------------------------
// Fused kernel. grid = 128 (b*4+q), block = 512, 1 CTA/SM.
// ---------------------------------------------------------------------------
__global__ void __launch_bounds__(THREADS, 1) fused_kernel(
    const float* __restrict__ x,      // [B, D, N]
    const float* __restrict__ w,      // [K, D]
    const float* __restrict__ bias)   // [K]
{
    extern __shared__ char sm[];
    __half* ws    = (__half*)(sm + WS_OFF);
    char*   xdn   = sm + XDN_OFF;               // fp16 [512] rows of 144B
    float*  at    = (float*)(sm + AT_OFF);      // [64][68]
    char*   akp   = sm + AKP_OFF;               // fp16 [64] rows of 144B
    float*  asred = (float*)(sm + ASR_OFF);     // [8][72]
    const uint32_t xdn_u = smem_u32(xdn);
    const uint32_t ws_u  = smem_u32(ws);
    const uint32_t akp_u = smem_u32(akp);

    const int tid  = threadIdx.x;
    const int wid  = tid >> 5;
    const int lane = tid & 31;
    const int g    = lane >> 2;
    const int tg   = lane & 3;
    const int b    = blockIdx.x >> 2;
    const int q    = blockIdx.x & 3;

    // GEMM1: m-tile = 16 px (wid&3), n = 2 center-octets at n0
    const int p0 = (wid & 3) * 16;
    const int n0 = (wid >> 2) * 16;
    const float bias_a0 = bias[n0 + 2 * tg];
    const float bias_a1 = bias[n0 + 2 * tg + 1];
    const float bias_b0 = bias[n0 + 8 + 2 * tg];
    const float bias_b1 = bias[n0 + 8 + 2 * tg + 1];
    // A (x^T) via ldmatrix.x4.trans
    const uint32_t lmA1 = xdn_u
        + (uint32_t)(((lane >> 4) * 8 + (lane & 7)) * 144
                     + (p0 + ((lane >> 3) & 1) * 8) * 2);
    // B (w) via ldmatrix.x4: tiles = (oct0 k0-7, oct0 k8-15, oct1 k0-7, oct1 k8-15)
    const uint32_t lmB1 = ws_u
        + (uint32_t)((n0 + (lane & 7) + (lane >> 4) * 8) * 1040
                     + ((lane >> 3) & 1) * 16);

    // GEMM2: m-tile = 16 centers (wid&3), d span = (wid>>2)*128
    const int kb2   = (wid & 3) * 16;
    const int dbase = (wid >> 2) * 128;
    // A (alpha) canonical 16x16 ldmatrix.x4
    const uint32_t lmA2 = akp_u
        + (uint32_t)((kb2 + (lane & 15)) * 144 + (lane >> 4) * 16);
    // B (x^T) ldmatrix.x4: per jj covers d-octets 2jj, 2jj+1
    const uint32_t lmB2 = xdn_u
        + (uint32_t)((dbase + (lane & 7) + (lane >> 4) * 8) * 144
                     + ((lane >> 3) & 1) * 16);

    // ---- convert w -> fp16 ws once ------------------------------------------
#pragma unroll
    for (int r = 0; r < 16; ++r) {
        int idx = tid + r * THREADS;
        int k = idx >> 7;
        int j = idx & 127;
        float4 v = *(const float4*)(w + (size_t)k * DD + j * 4);
        uint2 u = cvt_f4h(v);
        *(uint2*)((char*)ws + k * 1040 + j * 8) = u;
    }

    // persistent vlad^T accumulators [16 d-octets][4]
    float c2[16][4];
#pragma unroll
    for (int j = 0; j < 16; ++j)
#pragma unroll
        for (int r = 0; r < 4; ++r) c2[j][r] = 0.0f;

    float asum_acc = 0.0f;
    const float* xg = x + (size_t)b * DD * NNPIX;
    const int jj = tid & 15;
    const int r0 = tid >> 4;

    // ---- prologue prefetch: first tile, rows 256-511 ------------------------
    float4 pf[8];
#pragma unroll
    for (int i = 0; i < 8; ++i)
        pf[i] = *(const float4*)(xg + (size_t)(256 + r0 + i * 32) * NNPIX
                                 + q * TNP + jj * 4);

    int lt = 0;
    for (int t = q; t < NTILES; t += CPB, ++lt) {
        __syncthreads();                       // (A) prev consumers of xdn/akp done

        if (lt > 0 && tid < KK) {
            float s = 0.0f;
#pragma unroll
            for (int i = 0; i < 8; ++i) s += asred[i * 72 + tid];
            asum_acc += s;
        }

        // ---- fill xdn: half2 from prefetch regs, half1 synchronous ----------
#pragma unroll
        for (int i = 0; i < 8; ++i) {
            int r = 256 + r0 + i * 32;
            uint2 u = cvt_f4h(pf[i]);
            *(uint2*)(xdn + r * 144 + jj * 8) = u;
        }
#pragma unroll
        for (int i = 0; i < 8; ++i) {
            int r = r0 + i * 32;
            float4 v = *(const float4*)(xg + (size_t)r * NNPIX + t * TNP + jj * 4);
            uint2 u = cvt_f4h(v);
            *(uint2*)(xdn + r * 144 + jj * 8) = u;
        }
        __syncthreads();                       // (B) xdn ready

        // ---- GEMM1: logits^T[64px][64k] = x^T @ w^T --------------------------
        {
            float c1a[4] = {0.f, 0.f, 0.f, 0.f};
            float c1b[4] = {0.f, 0.f, 0.f, 0.f};
#pragma unroll
            for (int ks = 0; ks < 32; ++ks) {
                uint32_t a0, a1, a2, a3, b0, b1, b2, b3;
                LDSM4T(a0, a1, a2, a3, lmA1 + (uint32_t)ks * 2304);
                LDSM4(b0, b1, b2, b3, lmB1 + (uint32_t)ks * 32);
                mma_f16(c1a, a0, a1, a2, a3, b0, b1);
                mma_f16(c1b, a0, a1, a2, a3, b2, b3);
            }
            float* atp = at + (p0 + g) * 68;
            atp[n0 + 2 * tg]              = c1a[0] + bias_a0;
            atp[n0 + 2 * tg + 1]          = c1a[1] + bias_a1;
            atp[8 * 68 + n0 + 2 * tg]     = c1a[2] + bias_a0;
            atp[8 * 68 + n0 + 2 * tg + 1] = c1a[3] + bias_a1;
            atp[n0 + 8 + 2 * tg]              = c1b[0] + bias_b0;
            atp[n0 + 8 + 2 * tg + 1]          = c1b[1] + bias_b1;
            atp[8 * 68 + n0 + 8 + 2 * tg]     = c1b[2] + bias_b0;
            atp[8 * 68 + n0 + 8 + 2 * tg + 1] = c1b[3] + bias_b1;
        }
        __syncthreads();                       // (C) logits staged

        // ---- softmax over k per pixel ----------------------------------------
#pragma unroll
        for (int pp = 0; pp < 4; ++pp) {
            int p = wid * 4 + pp;
            float v0 = at[p * 68 + lane];
            float v1 = at[p * 68 + lane + 32];
            float m = fmaxf(v0, v1);
#pragma unroll
            for (int off = 16; off > 0; off >>= 1)
                m = fmaxf(m, __shfl_xor_sync(0xFFFFFFFFu, m, off));
            float e0 = __expf(v0 - m);
            float e1 = __expf(v1 - m);
            float s = e0 + e1;
#pragma unroll
            for (int off = 16; off > 0; off >>= 1)
                s += __shfl_xor_sync(0xFFFFFFFFu, s, off);
            float inv = 1.0f / s;
            *(__half*)(akp + lane * 144 + p * 2)        = __float2half_rn(e0 * inv);
            *(__half*)(akp + (lane + 32) * 144 + p * 2) = __float2half_rn(e1 * inv);
        }
        __syncthreads();                       // (D) alpha ready

        // ---- prefetch next tile rows 256-511 (lands during GEMM2) -----------
        if (t + CPB < NTILES) {
#pragma unroll
            for (int i = 0; i < 8; ++i)
                pf[i] = *(const float4*)(xg + (size_t)(256 + r0 + i * 32) * NNPIX
                                         + (t + CPB) * TNP + jj * 4);
        }

        // ---- asum partials ----------------------------------------------------
        {
            int k = tid & 63;
            int grp = tid >> 6;
            uint4 u = *(const uint4*)(akp + k * 144 + grp * 16);
            float2 f0 = __half22float2(*(__half2*)&u.x);
            float2 f1 = __half22float2(*(__half2*)&u.y);
            float2 f2 = __half22float2(*(__half2*)&u.z);
            float2 f3 = __half22float2(*(__half2*)&u.w);
            asred[grp * 72 + k] = (f0.x + f0.y) + (f1.x + f1.y)
                                + (f2.x + f2.y) + (f3.x + f3.y);
        }

        // ---- GEMM2: vlad^T[64k][512d] += alpha @ x^T --------------------------
#pragma unroll
        for (int s = 0; s < 4; ++s) {
            uint32_t a0, a1, a2, a3;
            LDSM4(a0, a1, a2, a3, lmA2 + (uint32_t)s * 32);
#pragma unroll
            for (int j2 = 0; j2 < 8; ++j2) {
                uint32_t b0, b1, b2, b3;
                LDSM4(b0, b1, b2, b3, lmB2 + (uint32_t)(j2 * 2304 + s * 32));
                mma_f16(c2[2 * j2],     a0, a1, a2, a3, b0, b1);
                mma_f16(c2[2 * j2 + 1], a0, a1, a2, a3, b2, b3);
            }
        }
    }

    __syncthreads();
    if (tid < KK) {
        float s = 0.0f;
#pragma unroll
        for (int i = 0; i < 8; ++i) s += asred[i * 72 + tid];
        g_asum_part[blockIdx.x * KK + tid] = asum_acc + s;
    }

    // ---- epilogue: transpose-stage vlad^T -> g_part[cta][d][k] --------------
    float* stage = (float*)xdn;                // [128][72] f32
    float* dstb = g_part + (size_t)blockIdx.x * DD * KK;
    for (int chunk = 0; chunk < 4; ++chunk) {
        __syncthreads();
        if ((wid >> 2) == chunk) {
#pragma unroll
            for (int j = 0; j < 16; ++j) {
                int dl = 8 * j + 2 * tg;
                stage[dl * 72 + kb2 + g]           = c2[j][0];
                stage[(dl + 1) * 72 + kb2 + g]     = c2[j][1];
                stage[dl * 72 + kb2 + g + 8]       = c2[j][2];
                stage[(dl + 1) * 72 + kb2 + g + 8] = c2[j][3];
            }
        }
        __syncthreads();
        float* dst = dstb + (size_t)chunk * 128 * KK;
#pragma unroll
        for (int r = 0; r < 4; ++r) {
            int i = tid + r * THREADS;
            int dl = i >> 4;
            int k4 = (i & 15) * 4;
            float4 v = *(float4*)&stage[dl * 72 + k4];
            *(float4*)&dst[(size_t)dl * KK + k4] = v;
        }
    }
}

// ---------------------------------------------------------------------------
// Epilogue A: y = sum_q part - centers*asum ; per-slice sumsq partials.
// ---------------------------------------------------------------------------
__global__ void reduce_y_kernel(const float* __restrict__ centers) {
    const int sl = blockIdx.x;
    const int b  = blockIdx.y;
    const int k  = threadIdx.x & 63;
    const int dg = threadIdx.x >> 6;

    float a = g_asum_part[(b * 4 + 0) * KK + k]
            + g_asum_part[(b * 4 + 1) * KK + k]
            + g_asum_part[(b * 4 + 2) * KK + k]
            + g_asum_part[(b * 4 + 3) * KK + k];

    const float* p0 = g_part + (size_t)(b * 4 + 0) * DD * KK;
    const float* p1 = g_part + (size_t)(b * 4 + 1) * DD * KK;
    const float* p2 = g_part + (size_t)(b * 4 + 2) * DD * KK;
    const float* p3 = g_part + (size_t)(b * 4 + 3) * DD * KK;
    float* yb = g_y + (size_t)b * DD * KK;

    float ss = 0.0f;
#pragma unroll
    for (int i = 0; i < 8; ++i) {
        int d = sl * 32 + dg * 8 + i;
        size_t o = (size_t)d * KK + k;
        float y = p0[o] + p1[o] + p2[o] + p3[o] - centers[o] * a;
        yb[o] = y;
        ss += y * y;
    }
    __shared__ float red[4][KK];
    red[dg][k] = ss;
    __syncthreads();
    if (threadIdx.x < KK)
        g_red[(b * 16 + sl) * KK + k] = red[0][k] + red[1][k] + red[2][k] + red[3][k];
}

// ---------------------------------------------------------------------------
// Epilogue B: cnorm + scale. Global norm == sqrt(K)=8 -> fold 1/8.
// ---------------------------------------------------------------------------
__global__ void scale_kernel(float* __restrict__ out) {
    const int sl = blockIdx.x;
    const int b  = blockIdx.y;
    __shared__ float cns[KK];
    if (threadIdx.x < KK) {
        float s = 0.0f;
#pragma unroll
        for (int j = 0; j < 16; ++j) s += g_red[(b * 16 + j) * KK + threadIdx.x];
        cns[threadIdx.x] = 0.125f * rsqrtf(s);
    }
    __syncthreads();

    const float* yb = g_y + (size_t)b * DD * KK + (size_t)sl * 32 * KK;
    float* ob = out + (size_t)b * DD * KK + (size_t)sl * 32 * KK;
#pragma unroll
    for (int r = 0; r < 2; ++r) {
        int i = threadIdx.x + r * 256;
        int k4 = (i & 15) * 4;
        float4 v = *(const float4*)(yb + (size_t)i * 4);
        v.x *= cns[k4];
        v.y *= cns[k4 + 1];
        v.z *= cns[k4 + 2];
        v.w *= cns[k4 + 3];
        *(float4*)(ob + (size_t)i * 4) = v;
    }
}

// ---------------------------------------------------------------------------
extern "C" void kernel_launch(void* const* d_in, const int* in_sizes, int n_in,
                              void* d_out, int out_size) {
    const float* x       = (const float*)d_in[0];
    const float* w       = (const float*)d_in[1];
    const float* bias    = (const float*)d_in[2];
    const float* centers = (const float*)d_in[3];
    float* out = (float*)d_out;

    cudaFuncSetAttribute(fused_kernel,
                         cudaFuncAttributeMaxDynamicSharedMemorySize, SMEM_BYTES);

    fused_kernel<<<BB * CPB, THREADS, SMEM_BYTES>>>(x, w, bias);
    reduce_y_kernel<<<dim3(16, BB), 256>>>(centers);
    scale_kernel<<<dim3(16, BB), 256>>>(out);
}